// round 1
// baseline (speedup 1.0000x reference)
#include <cuda_runtime.h>
#include <cuda_bf16.h>
#include <math.h>

// ---------------- problem constants ----------------
#define N_NODES   100000
#define N_EDGES   1600000
#define IN_DIM    256
#define OUT_DIM   128
#define NEG_SLOPE 0.2f
#define LAMBDA    0.5f
#define EPS_      1e-8f

// ---------------- device scratch (static, no allocs) ----------------
__device__ float g_h [(size_t)N_NODES * OUT_DIM];   // x @ W_gat^T
__device__ float g_xw[(size_t)N_NODES * OUT_DIM];   // x @ W_fixed^T
__device__ float g_asrc[N_NODES];
__device__ float g_adst[N_NODES];
__device__ float g_denom[N_NODES];
__device__ float g_alpha[N_EDGES];
__device__ int   g_src[N_EDGES];
__device__ int   g_dst[N_EDGES];
__device__ int   g_is64;

// ---------------- kernel 0: sniff edge_index dtype ----------------
// If edge_index is int64 (little-endian, values in [0, 1e5)), every odd 32-bit
// word is zero. If int32, odd words are random node ids — all-zero over 64
// samples has probability ~(1e-5)^64 ~= 0.
__global__ void k_sniff(const int* __restrict__ ei_words) {
    if (threadIdx.x == 0 && blockIdx.x == 0) {
        int allzero = 1;
        #pragma unroll 1
        for (int i = 0; i < 64; i++) {
            if (ei_words[2 * i + 1] != 0) { allzero = 0; break; }
        }
        g_is64 = allzero;
    }
}

// ---------------- kernel 1: convert edges to int32 ----------------
__global__ void k_convert(const void* __restrict__ ei) {
    int e = blockIdx.x * blockDim.x + threadIdx.x;
    if (e >= N_EDGES) return;
    if (g_is64) {
        const long long* p = (const long long*)ei;
        g_src[e] = (int)p[e];
        g_dst[e] = (int)p[(size_t)N_EDGES + e];
    } else {
        const int* p = (const int*)ei;
        g_src[e] = p[e];
        g_dst[e] = p[N_EDGES + e];
    }
}

// ---------------- kernel 2: zero out + denom ----------------
__global__ void k_zero(float* __restrict__ out) {
    size_t idx = (size_t)blockIdx.x * blockDim.x + threadIdx.x;
    const size_t n_out = (size_t)N_NODES * OUT_DIM;
    if (idx < n_out) out[idx] = 0.0f;
    else if (idx < n_out + N_NODES) g_denom[idx - n_out] = 0.0f;
}

// ---------------- kernel 3: dual GEMM ----------------
// C[m][n] = sum_k X[m][k] * W[n][k];  blockIdx.y selects (W_gat -> g_h) or
// (W_fixed -> g_xw). BM=128, BN=128(=OUT_DIM), BK=32, 256 thr, 8x8 microtile.
#define BM 128
#define BN 128
#define BK 32
__global__ __launch_bounds__(256, 2)
void k_gemm(const float* __restrict__ X,
            const float* __restrict__ Wg,
            const float* __restrict__ Wf) {
    __shared__ float As[BK][BM];
    __shared__ float Bs[BK][BN];

    const float* W = (blockIdx.y == 0) ? Wg : Wf;
    float*       C = (blockIdx.y == 0) ? g_h : g_xw;

    const int row0 = blockIdx.x * BM;
    const int tid  = threadIdx.x;
    const int tm   = (tid >> 4) << 3;   // 0..120
    const int tn   = (tid & 15) << 3;   // 0..120

    float acc[8][8];
    #pragma unroll
    for (int i = 0; i < 8; i++)
        #pragma unroll
        for (int j = 0; j < 8; j++) acc[i][j] = 0.0f;

    for (int k0 = 0; k0 < IN_DIM; k0 += BK) {
        // A tile: 128 rows x 32 k  (1024 float4, 4 per thread)
        #pragma unroll
        for (int i = 0; i < 4; i++) {
            int idx = tid + i * 256;
            int m   = idx >> 3;
            int k4  = (idx & 7) << 2;
            int gm  = row0 + m;
            float4 v = make_float4(0.f, 0.f, 0.f, 0.f);
            if (gm < N_NODES)
                v = *(const float4*)(X + (size_t)gm * IN_DIM + k0 + k4);
            As[k4 + 0][m] = v.x; As[k4 + 1][m] = v.y;
            As[k4 + 2][m] = v.z; As[k4 + 3][m] = v.w;
        }
        // B tile: 128 n-rows x 32 k
        #pragma unroll
        for (int i = 0; i < 4; i++) {
            int idx = tid + i * 256;
            int n   = idx >> 3;
            int k4  = (idx & 7) << 2;
            float4 v = *(const float4*)(W + (size_t)n * IN_DIM + k0 + k4);
            Bs[k4 + 0][n] = v.x; Bs[k4 + 1][n] = v.y;
            Bs[k4 + 2][n] = v.z; Bs[k4 + 3][n] = v.w;
        }
        __syncthreads();

        #pragma unroll
        for (int kk = 0; kk < BK; kk++) {
            float4 a0 = *(const float4*)&As[kk][tm];
            float4 a1 = *(const float4*)&As[kk][tm + 4];
            float4 b0 = *(const float4*)&Bs[kk][tn];
            float4 b1 = *(const float4*)&Bs[kk][tn + 4];
            float a[8] = {a0.x, a0.y, a0.z, a0.w, a1.x, a1.y, a1.z, a1.w};
            float b[8] = {b0.x, b0.y, b0.z, b0.w, b1.x, b1.y, b1.z, b1.w};
            #pragma unroll
            for (int i = 0; i < 8; i++)
                #pragma unroll
                for (int j = 0; j < 8; j++)
                    acc[i][j] = fmaf(a[i], b[j], acc[i][j]);
        }
        __syncthreads();
    }

    #pragma unroll
    for (int i = 0; i < 8; i++) {
        int gm = row0 + tm + i;
        if (gm < N_NODES) {
            float4 v0 = make_float4(acc[i][0], acc[i][1], acc[i][2], acc[i][3]);
            float4 v1 = make_float4(acc[i][4], acc[i][5], acc[i][6], acc[i][7]);
            *(float4*)(C + (size_t)gm * OUT_DIM + tn)     = v0;
            *(float4*)(C + (size_t)gm * OUT_DIM + tn + 4) = v1;
        }
    }
}

// ---------------- kernel 4: per-node attention scalars ----------------
// a_src[n] = h[n] . att_src ; a_dst[n] = h[n] . att_dst  (warp per node)
__global__ void k_attdot(const float* __restrict__ att_s,
                         const float* __restrict__ att_d) {
    int warp = (blockIdx.x * blockDim.x + threadIdx.x) >> 5;
    int lane = threadIdx.x & 31;
    if (warp >= N_NODES) return;
    float4 hv = *(const float4*)(g_h + (size_t)warp * OUT_DIM + lane * 4);
    float4 as = *(const float4*)(att_s + lane * 4);
    float4 ad = *(const float4*)(att_d + lane * 4);
    float s = hv.x * as.x + hv.y * as.y + hv.z * as.z + hv.w * as.w;
    float d = hv.x * ad.x + hv.y * ad.y + hv.z * ad.z + hv.w * ad.w;
    #pragma unroll
    for (int o = 16; o; o >>= 1) {
        s += __shfl_xor_sync(0xffffffffu, s, o);
        d += __shfl_xor_sync(0xffffffffu, d, o);
    }
    if (lane == 0) { g_asrc[warp] = s; g_adst[warp] = d; }
}

// ---------------- kernel 5: edge pass 1 (alpha + denom) ----------------
__global__ void k_edge1() {
    int e = blockIdx.x * blockDim.x + threadIdx.x;
    if (e >= N_EDGES) return;
    int s = g_src[e], d = g_dst[e];
    float x = g_asrc[s] + g_adst[d];
    if (x < 0.0f) x *= NEG_SLOPE;          // LeakyReLU
    float al = 1.0f / (1.0f + expf(-x));   // sigmoid
    g_alpha[e] = al;
    atomicAdd(&g_denom[d], al);
}

// ---------------- kernel 6: edge pass 2 (fused aggregation) ----------------
// warp per edge; lane handles 4 contiguous dims; scatter via red.global.v4
__global__ __launch_bounds__(256)
void k_edge2(const float* __restrict__ beta, float* __restrict__ out) {
    int e = blockIdx.x * 8 + (threadIdx.x >> 5);
    if (e >= N_EDGES) return;
    int lane = threadIdx.x & 31;
    int s = g_src[e], d = g_dst[e];
    float coefA = LAMBDA * g_alpha[e] / (g_denom[d] + EPS_);
    float coefB = (1.0f - LAMBDA) * beta[e];
    float4 h4 = __ldg((const float4*)(g_h  + (size_t)s * OUT_DIM) + lane);
    float4 x4 = __ldg((const float4*)(g_xw + (size_t)s * OUT_DIM) + lane);
    float4 v;
    v.x = coefA * h4.x + coefB * x4.x;
    v.y = coefA * h4.y + coefB * x4.y;
    v.z = coefA * h4.z + coefB * x4.z;
    v.w = coefA * h4.w + coefB * x4.w;
    float* op = out + (size_t)d * OUT_DIM + lane * 4;
    asm volatile("red.global.add.v4.f32 [%0], {%1, %2, %3, %4};"
                 :: "l"(op), "f"(v.x), "f"(v.y), "f"(v.z), "f"(v.w)
                 : "memory");
}

// ---------------- kernel 7: finalize (bias + elu) ----------------
__global__ void k_final(const float* __restrict__ bias, float* __restrict__ out) {
    size_t idx = (size_t)blockIdx.x * blockDim.x + threadIdx.x;
    if (idx >= (size_t)N_NODES * OUT_DIM) return;
    float v = out[idx] + LAMBDA * bias[idx & (OUT_DIM - 1)];
    out[idx] = (v > 0.0f) ? v : expm1f(v);
}

// ---------------- launch ----------------
extern "C" void kernel_launch(void* const* d_in, const int* in_sizes, int n_in,
                              void* d_out, int out_size) {
    const float* x       = (const float*)d_in[0];
    const void*  ei      = d_in[1];
    const float* beta    = (const float*)d_in[2];
    const float* W_gat   = (const float*)d_in[3];
    const float* att_src = (const float*)d_in[4];
    const float* att_dst = (const float*)d_in[5];
    const float* bias    = (const float*)d_in[6];
    const float* W_fixed = (const float*)d_in[7];
    float* out = (float*)d_out;

    // 0: dtype sniff + edge convert
    k_sniff<<<1, 32>>>((const int*)ei);
    k_convert<<<(N_EDGES + 255) / 256, 256>>>(ei);

    // 1: zero out + denom
    {
        size_t total = (size_t)N_NODES * OUT_DIM + N_NODES;
        k_zero<<<(int)((total + 255) / 256), 256>>>(out);
    }

    // 2: dual GEMM  (h = x W_gat^T, xw = x W_fixed^T)
    {
        dim3 grid((N_NODES + BM - 1) / BM, 2);
        k_gemm<<<grid, 256>>>(x, W_gat, W_fixed);
    }

    // 3: per-node attention scalars
    k_attdot<<<(N_NODES * 32 + 255) / 256, 256>>>(att_src, att_dst);

    // 4: edge pass 1
    k_edge1<<<(N_EDGES + 255) / 256, 256>>>();

    // 5: edge pass 2 (fused dual aggregation)
    k_edge2<<<(N_EDGES + 7) / 8, 256>>>(beta, out);

    // 6: finalize
    k_final<<<((size_t)N_NODES * OUT_DIM + 255) / 256, 256>>>(bias, out);
}

// round 2
// speedup vs baseline: 1.7414x; 1.7414x over previous
#include <cuda_runtime.h>
#include <cuda_bf16.h>
#include <math.h>
#include <stdint.h>

// ---------------- problem constants ----------------
#define N_NODES   100000
#define N_EDGES   1600000
#define IN_DIM    256
#define OUT_DIM   128
#define NEG_SLOPE 0.2f
#define LAMBDA    0.5f
#define EPS_      1e-8f

// ---------------- device scratch (static, no allocs) ----------------
__device__ float g_h [(size_t)N_NODES * OUT_DIM];   // x @ W_gat^T
__device__ float g_xw[(size_t)N_NODES * OUT_DIM];   // x @ W_fixed^T
__device__ float g_asrc[N_NODES];
__device__ float g_adst[N_NODES];
__device__ float g_denom[N_NODES];
__device__ float g_alpha[N_EDGES];
__device__ int   g_src[N_EDGES];
__device__ int   g_dst[N_EDGES];
__device__ int   g_is64;

// ---------------- kernel 0: sniff edge_index dtype ----------------
__global__ void k_sniff(const int* __restrict__ ei_words) {
    if (threadIdx.x == 0 && blockIdx.x == 0) {
        int allzero = 1;
        #pragma unroll 1
        for (int i = 0; i < 64; i++) {
            if (ei_words[2 * i + 1] != 0) { allzero = 0; break; }
        }
        g_is64 = allzero;
    }
}

// ---------------- kernel 1: convert edges to int32 ----------------
__global__ void k_convert(const void* __restrict__ ei) {
    int e = blockIdx.x * blockDim.x + threadIdx.x;
    if (e >= N_EDGES) return;
    if (g_is64) {
        const long long* p = (const long long*)ei;
        g_src[e] = (int)p[e];
        g_dst[e] = (int)p[(size_t)N_EDGES + e];
    } else {
        const int* p = (const int*)ei;
        g_src[e] = p[e];
        g_dst[e] = p[N_EDGES + e];
    }
}

// ---------------- kernel 2: zero out + denom ----------------
__global__ void k_zero(float* __restrict__ out) {
    size_t idx = (size_t)blockIdx.x * blockDim.x + threadIdx.x;
    const size_t n_out = (size_t)N_NODES * OUT_DIM;
    if (idx < n_out) out[idx] = 0.0f;
    else if (idx < n_out + N_NODES) g_denom[idx - n_out] = 0.0f;
}

// ---------------- tf32 helpers ----------------
__device__ __forceinline__ void tf32_split(float v, uint32_t& hi, uint32_t& lo) {
    asm("cvt.rna.tf32.f32 %0, %1;" : "=r"(hi) : "f"(v));
    float l = v - __uint_as_float(hi);
    asm("cvt.rna.tf32.f32 %0, %1;" : "=r"(lo) : "f"(l));
}

__device__ __forceinline__ void mma_tf32(float* d, const uint32_t* a,
                                         uint32_t b0, uint32_t b1) {
    asm volatile(
        "mma.sync.aligned.m16n8k8.row.col.f32.tf32.tf32.f32 "
        "{%0,%1,%2,%3}, {%4,%5,%6,%7}, {%8,%9}, {%0,%1,%2,%3};\n"
        : "+f"(d[0]), "+f"(d[1]), "+f"(d[2]), "+f"(d[3])
        : "r"(a[0]), "r"(a[1]), "r"(a[2]), "r"(a[3]), "r"(b0), "r"(b1));
}

// ---------------- kernel 3: dual GEMM on tensor cores ----------------
// C[m][n] = sum_k X[m][k] * W[n][k] via 3-term tf32 split (fp32-grade accuracy).
// CTA tile 128x128, BK=32, 8 warps in 4(M) x 2(N), warp tile 32x64.
#define GBM 128
#define GBK 32
#define PADK 36   // 32 + 4 pad -> (4*r + c) mod 32 hits all banks: conflict-free
#define SMEM_GEMM (4 * GBM * PADK * (int)sizeof(float))   // 73728 bytes

__global__ __launch_bounds__(256, 2)
void k_gemm_tc(const float* __restrict__ X,
               const float* __restrict__ Wg,
               const float* __restrict__ Wf) {
    extern __shared__ float smem[];
    float (*Ahi)[PADK] = (float(*)[PADK])(smem);
    float (*Alo)[PADK] = (float(*)[PADK])(smem + 1 * GBM * PADK);
    float (*Bhi)[PADK] = (float(*)[PADK])(smem + 2 * GBM * PADK);
    float (*Blo)[PADK] = (float(*)[PADK])(smem + 3 * GBM * PADK);

    const float* W = (blockIdx.y == 0) ? Wg : Wf;
    float*       C = (blockIdx.y == 0) ? g_h : g_xw;

    const int row0 = blockIdx.x * GBM;
    const int tid  = threadIdx.x;
    const int warp = tid >> 5, lane = tid & 31;
    const int wm = warp & 3;          // 0..3 -> 32-row slice
    const int wn = warp >> 2;         // 0..1 -> 64-col slice
    const int gid = lane >> 2;        // 0..7
    const int tig = lane & 3;         // 0..3

    float acc[2][8][4];
    #pragma unroll
    for (int mi = 0; mi < 2; mi++)
        #pragma unroll
        for (int ni = 0; ni < 8; ni++)
            #pragma unroll
            for (int j = 0; j < 4; j++) acc[mi][ni][j] = 0.0f;

    for (int k0 = 0; k0 < IN_DIM; k0 += GBK) {
        // ---- fill A tile (128 x 32) with hi/lo split ----
        #pragma unroll
        for (int i = 0; i < 4; i++) {
            int idx = tid + i * 256;          // 0..1023
            int m   = idx >> 3;               // 0..127
            int k4  = (idx & 7) << 2;         // 0,4,..,28
            float4 v = make_float4(0.f, 0.f, 0.f, 0.f);
            if (row0 + m < N_NODES)
                v = *(const float4*)(X + (size_t)(row0 + m) * IN_DIM + k0 + k4);
            uint32_t h, l;
            tf32_split(v.x, h, l); Ahi[m][k4+0] = __uint_as_float(h); Alo[m][k4+0] = __uint_as_float(l);
            tf32_split(v.y, h, l); Ahi[m][k4+1] = __uint_as_float(h); Alo[m][k4+1] = __uint_as_float(l);
            tf32_split(v.z, h, l); Ahi[m][k4+2] = __uint_as_float(h); Alo[m][k4+2] = __uint_as_float(l);
            tf32_split(v.w, h, l); Ahi[m][k4+3] = __uint_as_float(h); Alo[m][k4+3] = __uint_as_float(l);
        }
        // ---- fill B tile (128 n-rows x 32 k) ----
        #pragma unroll
        for (int i = 0; i < 4; i++) {
            int idx = tid + i * 256;
            int n   = idx >> 3;
            int k4  = (idx & 7) << 2;
            float4 v = *(const float4*)(W + (size_t)n * IN_DIM + k0 + k4);
            uint32_t h, l;
            tf32_split(v.x, h, l); Bhi[n][k4+0] = __uint_as_float(h); Blo[n][k4+0] = __uint_as_float(l);
            tf32_split(v.y, h, l); Bhi[n][k4+1] = __uint_as_float(h); Blo[n][k4+1] = __uint_as_float(l);
            tf32_split(v.z, h, l); Bhi[n][k4+2] = __uint_as_float(h); Blo[n][k4+2] = __uint_as_float(l);
            tf32_split(v.w, h, l); Bhi[n][k4+3] = __uint_as_float(h); Blo[n][k4+3] = __uint_as_float(l);
        }
        __syncthreads();

        #pragma unroll
        for (int ks = 0; ks < 4; ks++) {
            const int kk = ks * 8;
            // A fragments (hi and lo) for both 16-row sub-tiles
            uint32_t ah[2][4], al[2][4];
            #pragma unroll
            for (int mi = 0; mi < 2; mi++) {
                int r = wm * 32 + mi * 16 + gid;
                ah[mi][0] = __float_as_uint(Ahi[r    ][kk + tig    ]);
                ah[mi][1] = __float_as_uint(Ahi[r + 8][kk + tig    ]);
                ah[mi][2] = __float_as_uint(Ahi[r    ][kk + tig + 4]);
                ah[mi][3] = __float_as_uint(Ahi[r + 8][kk + tig + 4]);
                al[mi][0] = __float_as_uint(Alo[r    ][kk + tig    ]);
                al[mi][1] = __float_as_uint(Alo[r + 8][kk + tig    ]);
                al[mi][2] = __float_as_uint(Alo[r    ][kk + tig + 4]);
                al[mi][3] = __float_as_uint(Alo[r + 8][kk + tig + 4]);
            }
            #pragma unroll
            for (int ni = 0; ni < 8; ni++) {
                int n = wn * 64 + ni * 8 + gid;
                uint32_t bh0 = __float_as_uint(Bhi[n][kk + tig    ]);
                uint32_t bh1 = __float_as_uint(Bhi[n][kk + tig + 4]);
                uint32_t bl0 = __float_as_uint(Blo[n][kk + tig    ]);
                uint32_t bl1 = __float_as_uint(Blo[n][kk + tig + 4]);
                #pragma unroll
                for (int mi = 0; mi < 2; mi++) {
                    mma_tf32(acc[mi][ni], ah[mi], bh0, bh1);   // hi*hi
                    mma_tf32(acc[mi][ni], al[mi], bh0, bh1);   // lo*hi
                    mma_tf32(acc[mi][ni], ah[mi], bl0, bl1);   // hi*lo
                }
            }
        }
        __syncthreads();
    }

    // ---- epilogue ----
    #pragma unroll
    for (int mi = 0; mi < 2; mi++) {
        #pragma unroll
        for (int ni = 0; ni < 8; ni++) {
            int col = wn * 64 + ni * 8 + 2 * tig;
            int r0  = row0 + wm * 32 + mi * 16 + gid;
            if (r0 < N_NODES)
                *(float2*)(C + (size_t)r0 * OUT_DIM + col) =
                    make_float2(acc[mi][ni][0], acc[mi][ni][1]);
            int r1 = r0 + 8;
            if (r1 < N_NODES)
                *(float2*)(C + (size_t)r1 * OUT_DIM + col) =
                    make_float2(acc[mi][ni][2], acc[mi][ni][3]);
        }
    }
}

// ---------------- kernel 4: per-node attention scalars ----------------
__global__ void k_attdot(const float* __restrict__ att_s,
                         const float* __restrict__ att_d) {
    int warp = (blockIdx.x * blockDim.x + threadIdx.x) >> 5;
    int lane = threadIdx.x & 31;
    if (warp >= N_NODES) return;
    float4 hv = *(const float4*)(g_h + (size_t)warp * OUT_DIM + lane * 4);
    float4 as = *(const float4*)(att_s + lane * 4);
    float4 ad = *(const float4*)(att_d + lane * 4);
    float s = hv.x * as.x + hv.y * as.y + hv.z * as.z + hv.w * as.w;
    float d = hv.x * ad.x + hv.y * ad.y + hv.z * ad.z + hv.w * ad.w;
    #pragma unroll
    for (int o = 16; o; o >>= 1) {
        s += __shfl_xor_sync(0xffffffffu, s, o);
        d += __shfl_xor_sync(0xffffffffu, d, o);
    }
    if (lane == 0) { g_asrc[warp] = s; g_adst[warp] = d; }
}

// ---------------- kernel 5: edge pass 1 (alpha + denom) ----------------
__global__ void k_edge1() {
    int e = blockIdx.x * blockDim.x + threadIdx.x;
    if (e >= N_EDGES) return;
    int s = g_src[e], d = g_dst[e];
    float x = g_asrc[s] + g_adst[d];
    if (x < 0.0f) x *= NEG_SLOPE;          // LeakyReLU
    float al = 1.0f / (1.0f + expf(-x));   // sigmoid
    g_alpha[e] = al;
    atomicAdd(&g_denom[d], al);
}

// ---------------- kernel 6: edge pass 2 (fused aggregation) ----------------
__global__ __launch_bounds__(256)
void k_edge2(const float* __restrict__ beta, float* __restrict__ out) {
    int e = blockIdx.x * 8 + (threadIdx.x >> 5);
    if (e >= N_EDGES) return;
    int lane = threadIdx.x & 31;
    int s = g_src[e], d = g_dst[e];
    float coefA = LAMBDA * g_alpha[e] / (g_denom[d] + EPS_);
    float coefB = (1.0f - LAMBDA) * beta[e];
    float4 h4 = __ldg((const float4*)(g_h  + (size_t)s * OUT_DIM) + lane);
    float4 x4 = __ldg((const float4*)(g_xw + (size_t)s * OUT_DIM) + lane);
    float4 v;
    v.x = coefA * h4.x + coefB * x4.x;
    v.y = coefA * h4.y + coefB * x4.y;
    v.z = coefA * h4.z + coefB * x4.z;
    v.w = coefA * h4.w + coefB * x4.w;
    float* op = out + (size_t)d * OUT_DIM + lane * 4;
    asm volatile("red.global.add.v4.f32 [%0], {%1, %2, %3, %4};"
                 :: "l"(op), "f"(v.x), "f"(v.y), "f"(v.z), "f"(v.w)
                 : "memory");
}

// ---------------- kernel 7: finalize (bias + elu) ----------------
__global__ void k_final(const float* __restrict__ bias, float* __restrict__ out) {
    size_t idx = (size_t)blockIdx.x * blockDim.x + threadIdx.x;
    if (idx >= (size_t)N_NODES * OUT_DIM) return;
    float v = out[idx] + LAMBDA * bias[idx & (OUT_DIM - 1)];
    out[idx] = (v > 0.0f) ? v : expm1f(v);
}

// ---------------- launch ----------------
extern "C" void kernel_launch(void* const* d_in, const int* in_sizes, int n_in,
                              void* d_out, int out_size) {
    const float* x       = (const float*)d_in[0];
    const void*  ei      = d_in[1];
    const float* beta    = (const float*)d_in[2];
    const float* W_gat   = (const float*)d_in[3];
    const float* att_src = (const float*)d_in[4];
    const float* att_dst = (const float*)d_in[5];
    const float* bias    = (const float*)d_in[6];
    const float* W_fixed = (const float*)d_in[7];
    float* out = (float*)d_out;

    static int smem_set = 0;
    if (!smem_set) {
        cudaFuncSetAttribute(k_gemm_tc,
                             cudaFuncAttributeMaxDynamicSharedMemorySize,
                             SMEM_GEMM);
        smem_set = 1;
    }

    // 0: dtype sniff + edge convert
    k_sniff<<<1, 32>>>((const int*)ei);
    k_convert<<<(N_EDGES + 255) / 256, 256>>>(ei);

    // 1: zero out + denom
    {
        size_t total = (size_t)N_NODES * OUT_DIM + N_NODES;
        k_zero<<<(int)((total + 255) / 256), 256>>>(out);
    }

    // 2: dual GEMM on tensor cores
    {
        dim3 grid((N_NODES + GBM - 1) / GBM, 2);
        k_gemm_tc<<<grid, 256, SMEM_GEMM>>>(x, W_gat, W_fixed);
    }

    // 3: per-node attention scalars
    k_attdot<<<(N_NODES * 32 + 255) / 256, 256>>>(att_src, att_dst);

    // 4: edge pass 1
    k_edge1<<<(N_EDGES + 255) / 256, 256>>>();

    // 5: edge pass 2 (fused dual aggregation)
    k_edge2<<<(N_EDGES + 7) / 8, 256>>>(beta, out);

    // 6: finalize
    k_final<<<((size_t)N_NODES * OUT_DIM + 255) / 256, 256>>>(bias, out);
}

// round 3
// speedup vs baseline: 2.3982x; 1.3771x over previous
#include <cuda_runtime.h>
#include <cuda_bf16.h>
#include <math.h>
#include <stdint.h>

// ---------------- problem constants ----------------
#define N_NODES   100000
#define N_EDGES   1600000
#define IN_DIM    256
#define OUT_DIM   128
#define NEG_SLOPE 0.2f
#define LAMBDA    0.5f
#define EPS_      1e-8f

// ---------------- device scratch (static, no allocs) ----------------
__device__ float g_h [(size_t)N_NODES * OUT_DIM];   // x @ W_gat^T
__device__ float g_xw[(size_t)N_NODES * OUT_DIM];   // x @ W_fixed^T
__device__ float g_asrc[N_NODES];
__device__ float g_adst[N_NODES];
__device__ int   g_src[N_EDGES];
__device__ int   g_dst[N_EDGES];
__device__ int   g_deg[N_NODES];
__device__ int   g_off[N_NODES];
__device__ int   g_cursor[N_NODES];
__device__ int   g_csr_src[N_EDGES];
__device__ float g_csr_beta[N_EDGES];
__device__ int   g_is64;

#define SCAN_B 1024
#define NCHUNK ((N_NODES + SCAN_B - 1) / SCAN_B)   // 98
__device__ int g_bsum[NCHUNK];

// ---------------- kernel 0: sniff edge_index dtype ----------------
__global__ void k_sniff(const int* __restrict__ ei_words) {
    if (threadIdx.x == 0 && blockIdx.x == 0) {
        int allzero = 1;
        #pragma unroll 1
        for (int i = 0; i < 64; i++) {
            if (ei_words[2 * i + 1] != 0) { allzero = 0; break; }
        }
        g_is64 = allzero;
    }
}

// ---------------- kernel 1: zero small scratch ----------------
__global__ void k_zero_misc() {
    int i = blockIdx.x * blockDim.x + threadIdx.x;
    if (i < N_NODES) {
        g_deg[i] = 0;
        g_cursor[i] = 0;
        g_asrc[i] = 0.0f;
        g_adst[i] = 0.0f;
    }
}

// ---------------- kernel 2: convert edges + degree histogram ----------------
__global__ void k_convert_hist(const void* __restrict__ ei) {
    int e = blockIdx.x * blockDim.x + threadIdx.x;
    if (e >= N_EDGES) return;
    int s, d;
    if (g_is64) {
        const long long* p = (const long long*)ei;
        s = (int)p[e];
        d = (int)p[(size_t)N_EDGES + e];
    } else {
        const int* p = (const int*)ei;
        s = p[e];
        d = p[N_EDGES + e];
    }
    g_src[e] = s;
    g_dst[e] = d;
    atomicAdd(&g_deg[d], 1);
}

// ---------------- tf32 helpers ----------------
__device__ __forceinline__ void tf32_split(float v, uint32_t& hi, uint32_t& lo) {
    asm("cvt.rna.tf32.f32 %0, %1;" : "=r"(hi) : "f"(v));
    float l = v - __uint_as_float(hi);
    asm("cvt.rna.tf32.f32 %0, %1;" : "=r"(lo) : "f"(l));
}

__device__ __forceinline__ void mma_tf32(float* d, const uint32_t* a,
                                         uint32_t b0, uint32_t b1) {
    asm volatile(
        "mma.sync.aligned.m16n8k8.row.col.f32.tf32.tf32.f32 "
        "{%0,%1,%2,%3}, {%4,%5,%6,%7}, {%8,%9}, {%0,%1,%2,%3};\n"
        : "+f"(d[0]), "+f"(d[1]), "+f"(d[2]), "+f"(d[3])
        : "r"(a[0]), "r"(a[1]), "r"(a[2]), "r"(a[3]), "r"(b0), "r"(b1));
}

// ---------------- kernel 3: dual GEMM on tensor cores ----------------
// C[m][n] = sum_k X[m][k]*W[n][k], 3-term tf32 split. For the attention branch
// (blockIdx.y==0) the per-node attention dots are fused into the epilogue.
#define GBM 128
#define GBK 32
#define PADK 36
#define SMEM_GEMM (4 * GBM * PADK * (int)sizeof(float))   // 73728 bytes

__global__ __launch_bounds__(256, 2)
void k_gemm_tc(const float* __restrict__ X,
               const float* __restrict__ Wg,
               const float* __restrict__ Wf,
               const float* __restrict__ att_s,
               const float* __restrict__ att_d) {
    extern __shared__ float smem[];
    float (*Ahi)[PADK] = (float(*)[PADK])(smem);
    float (*Alo)[PADK] = (float(*)[PADK])(smem + 1 * GBM * PADK);
    float (*Bhi)[PADK] = (float(*)[PADK])(smem + 2 * GBM * PADK);
    float (*Blo)[PADK] = (float(*)[PADK])(smem + 3 * GBM * PADK);

    const float* W = (blockIdx.y == 0) ? Wg : Wf;
    float*       C = (blockIdx.y == 0) ? g_h : g_xw;

    const int row0 = blockIdx.x * GBM;
    const int tid  = threadIdx.x;
    const int warp = tid >> 5, lane = tid & 31;
    const int wm = warp & 3;
    const int wn = warp >> 2;
    const int gid = lane >> 2;
    const int tig = lane & 3;

    float acc[2][8][4];
    #pragma unroll
    for (int mi = 0; mi < 2; mi++)
        #pragma unroll
        for (int ni = 0; ni < 8; ni++)
            #pragma unroll
            for (int j = 0; j < 4; j++) acc[mi][ni][j] = 0.0f;

    for (int k0 = 0; k0 < IN_DIM; k0 += GBK) {
        #pragma unroll
        for (int i = 0; i < 4; i++) {
            int idx = tid + i * 256;
            int m   = idx >> 3;
            int k4  = (idx & 7) << 2;
            float4 v = make_float4(0.f, 0.f, 0.f, 0.f);
            if (row0 + m < N_NODES)
                v = *(const float4*)(X + (size_t)(row0 + m) * IN_DIM + k0 + k4);
            uint32_t h, l;
            tf32_split(v.x, h, l); Ahi[m][k4+0] = __uint_as_float(h); Alo[m][k4+0] = __uint_as_float(l);
            tf32_split(v.y, h, l); Ahi[m][k4+1] = __uint_as_float(h); Alo[m][k4+1] = __uint_as_float(l);
            tf32_split(v.z, h, l); Ahi[m][k4+2] = __uint_as_float(h); Alo[m][k4+2] = __uint_as_float(l);
            tf32_split(v.w, h, l); Ahi[m][k4+3] = __uint_as_float(h); Alo[m][k4+3] = __uint_as_float(l);
        }
        #pragma unroll
        for (int i = 0; i < 4; i++) {
            int idx = tid + i * 256;
            int n   = idx >> 3;
            int k4  = (idx & 7) << 2;
            float4 v = *(const float4*)(W + (size_t)n * IN_DIM + k0 + k4);
            uint32_t h, l;
            tf32_split(v.x, h, l); Bhi[n][k4+0] = __uint_as_float(h); Blo[n][k4+0] = __uint_as_float(l);
            tf32_split(v.y, h, l); Bhi[n][k4+1] = __uint_as_float(h); Blo[n][k4+1] = __uint_as_float(l);
            tf32_split(v.z, h, l); Bhi[n][k4+2] = __uint_as_float(h); Blo[n][k4+2] = __uint_as_float(l);
            tf32_split(v.w, h, l); Bhi[n][k4+3] = __uint_as_float(h); Blo[n][k4+3] = __uint_as_float(l);
        }
        __syncthreads();

        #pragma unroll
        for (int ks = 0; ks < 4; ks++) {
            const int kk = ks * 8;
            uint32_t ah[2][4], al[2][4];
            #pragma unroll
            for (int mi = 0; mi < 2; mi++) {
                int r = wm * 32 + mi * 16 + gid;
                ah[mi][0] = __float_as_uint(Ahi[r    ][kk + tig    ]);
                ah[mi][1] = __float_as_uint(Ahi[r + 8][kk + tig    ]);
                ah[mi][2] = __float_as_uint(Ahi[r    ][kk + tig + 4]);
                ah[mi][3] = __float_as_uint(Ahi[r + 8][kk + tig + 4]);
                al[mi][0] = __float_as_uint(Alo[r    ][kk + tig    ]);
                al[mi][1] = __float_as_uint(Alo[r + 8][kk + tig    ]);
                al[mi][2] = __float_as_uint(Alo[r    ][kk + tig + 4]);
                al[mi][3] = __float_as_uint(Alo[r + 8][kk + tig + 4]);
            }
            #pragma unroll
            for (int ni = 0; ni < 8; ni++) {
                int n = wn * 64 + ni * 8 + gid;
                uint32_t bh0 = __float_as_uint(Bhi[n][kk + tig    ]);
                uint32_t bh1 = __float_as_uint(Bhi[n][kk + tig + 4]);
                uint32_t bl0 = __float_as_uint(Blo[n][kk + tig    ]);
                uint32_t bl1 = __float_as_uint(Blo[n][kk + tig + 4]);
                #pragma unroll
                for (int mi = 0; mi < 2; mi++) {
                    mma_tf32(acc[mi][ni], ah[mi], bh0, bh1);
                    mma_tf32(acc[mi][ni], al[mi], bh0, bh1);
                    mma_tf32(acc[mi][ni], ah[mi], bl0, bl1);
                }
            }
        }
        __syncthreads();
    }

    // ---- epilogue: store C ----
    #pragma unroll
    for (int mi = 0; mi < 2; mi++) {
        #pragma unroll
        for (int ni = 0; ni < 8; ni++) {
            int col = wn * 64 + ni * 8 + 2 * tig;
            int r0  = row0 + wm * 32 + mi * 16 + gid;
            if (r0 < N_NODES)
                *(float2*)(C + (size_t)r0 * OUT_DIM + col) =
                    make_float2(acc[mi][ni][0], acc[mi][ni][1]);
            int r1 = r0 + 8;
            if (r1 < N_NODES)
                *(float2*)(C + (size_t)r1 * OUT_DIM + col) =
                    make_float2(acc[mi][ni][2], acc[mi][ni][3]);
        }
    }

    // ---- fused attention dots (h branch only) ----
    if (blockIdx.y == 0) {
        #pragma unroll
        for (int mi = 0; mi < 2; mi++) {
            float s0 = 0.f, d0 = 0.f, s1 = 0.f, d1 = 0.f;
            #pragma unroll
            for (int ni = 0; ni < 8; ni++) {
                int col = wn * 64 + ni * 8 + 2 * tig;
                float a0 = __ldg(att_s + col), a1 = __ldg(att_s + col + 1);
                float b0 = __ldg(att_d + col), b1 = __ldg(att_d + col + 1);
                s0 += acc[mi][ni][0] * a0 + acc[mi][ni][1] * a1;
                d0 += acc[mi][ni][0] * b0 + acc[mi][ni][1] * b1;
                s1 += acc[mi][ni][2] * a0 + acc[mi][ni][3] * a1;
                d1 += acc[mi][ni][2] * b0 + acc[mi][ni][3] * b1;
            }
            // reduce across the 4 tig lanes of this gid group
            #pragma unroll
            for (int o = 1; o <= 2; o <<= 1) {
                s0 += __shfl_xor_sync(0xffffffffu, s0, o);
                d0 += __shfl_xor_sync(0xffffffffu, d0, o);
                s1 += __shfl_xor_sync(0xffffffffu, s1, o);
                d1 += __shfl_xor_sync(0xffffffffu, d1, o);
            }
            if (tig == 0) {
                int r0 = row0 + wm * 32 + mi * 16 + gid;
                if (r0 < N_NODES) {
                    atomicAdd(&g_asrc[r0], s0);
                    atomicAdd(&g_adst[r0], d0);
                }
                int r1 = r0 + 8;
                if (r1 < N_NODES) {
                    atomicAdd(&g_asrc[r1], s1);
                    atomicAdd(&g_adst[r1], d1);
                }
            }
        }
    }
}

// ---------------- scan kernels (exclusive prefix of g_deg -> g_off) --------
__global__ void k_scan1() {
    __shared__ int sh[SCAN_B];
    int i = blockIdx.x * SCAN_B + threadIdx.x;
    int v = (i < N_NODES) ? g_deg[i] : 0;
    sh[threadIdx.x] = v;
    __syncthreads();
    for (int o = 1; o < SCAN_B; o <<= 1) {
        int t = (threadIdx.x >= o) ? sh[threadIdx.x - o] : 0;
        __syncthreads();
        sh[threadIdx.x] += t;
        __syncthreads();
    }
    if (i < N_NODES) g_off[i] = sh[threadIdx.x] - v;
    if (threadIdx.x == SCAN_B - 1) g_bsum[blockIdx.x] = sh[threadIdx.x];
}

__global__ void k_scan2() {
    __shared__ int sh[128];
    int v = (threadIdx.x < NCHUNK) ? g_bsum[threadIdx.x] : 0;
    sh[threadIdx.x] = v;
    __syncthreads();
    for (int o = 1; o < 128; o <<= 1) {
        int t = (threadIdx.x >= o) ? sh[threadIdx.x - o] : 0;
        __syncthreads();
        sh[threadIdx.x] += t;
        __syncthreads();
    }
    if (threadIdx.x < NCHUNK) g_bsum[threadIdx.x] = sh[threadIdx.x] - v;
}

__global__ void k_scan3() {
    int i = blockIdx.x * SCAN_B + threadIdx.x;
    if (i < N_NODES) g_off[i] += g_bsum[blockIdx.x];
}

// ---------------- kernel: scatter edges into CSR ----------------
__global__ void k_scatter(const float* __restrict__ beta) {
    int e = blockIdx.x * blockDim.x + threadIdx.x;
    if (e >= N_EDGES) return;
    int d = g_dst[e];
    int pos = g_off[d] + atomicAdd(&g_cursor[d], 1);
    g_csr_src[pos]  = g_src[e];
    g_csr_beta[pos] = beta[e];
}

// ---------------- kernel: warp-per-node fused aggregation ----------------
__global__ __launch_bounds__(256)
void k_agg(const float* __restrict__ bias, float* __restrict__ out) {
    int node = (blockIdx.x * blockDim.x + threadIdx.x) >> 5;
    if (node >= N_NODES) return;
    int lane = threadIdx.x & 31;

    int beg = g_off[node];
    int deg = g_deg[node];
    float adst = g_adst[node];

    // phase 1: denom via lane-parallel alpha + warp reduce
    float psum = 0.0f;
    for (int i = beg + lane; i < beg + deg; i += 32) {
        int s = g_csr_src[i];
        float xv = g_asrc[s] + adst;
        if (xv < 0.0f) xv *= NEG_SLOPE;
        psum += 1.0f / (1.0f + expf(-xv));
    }
    #pragma unroll
    for (int o = 16; o; o >>= 1) psum += __shfl_xor_sync(0xffffffffu, psum, o);
    float invden = LAMBDA / (psum + EPS_);

    // phase 2: accumulate lam*alpha*h[src] + (1-lam)*beta*xw[src]
    float4 acc = make_float4(0.f, 0.f, 0.f, 0.f);
    #pragma unroll 2
    for (int i = beg; i < beg + deg; i++) {
        int s   = g_csr_src[i];           // warp-uniform broadcast load
        float b = g_csr_beta[i];
        float xv = g_asrc[s] + adst;
        if (xv < 0.0f) xv *= NEG_SLOPE;
        float al = 1.0f / (1.0f + expf(-xv));
        float cA = al * invden;
        float cB = (1.0f - LAMBDA) * b;
        float4 h4 = __ldg((const float4*)(g_h  + (size_t)s * OUT_DIM) + lane);
        float4 x4 = __ldg((const float4*)(g_xw + (size_t)s * OUT_DIM) + lane);
        acc.x += cA * h4.x + cB * x4.x;
        acc.y += cA * h4.y + cB * x4.y;
        acc.z += cA * h4.z + cB * x4.z;
        acc.w += cA * h4.w + cB * x4.w;
    }

    // epilogue: + lam*bias, ELU, single store
    float4 bv = *(const float4*)(bias + lane * 4);
    float4 v;
    v.x = acc.x + LAMBDA * bv.x;
    v.y = acc.y + LAMBDA * bv.y;
    v.z = acc.z + LAMBDA * bv.z;
    v.w = acc.w + LAMBDA * bv.w;
    v.x = (v.x > 0.0f) ? v.x : expm1f(v.x);
    v.y = (v.y > 0.0f) ? v.y : expm1f(v.y);
    v.z = (v.z > 0.0f) ? v.z : expm1f(v.z);
    v.w = (v.w > 0.0f) ? v.w : expm1f(v.w);
    *(float4*)(out + (size_t)node * OUT_DIM + lane * 4) = v;
}

// ---------------- launch ----------------
extern "C" void kernel_launch(void* const* d_in, const int* in_sizes, int n_in,
                              void* d_out, int out_size) {
    const float* x       = (const float*)d_in[0];
    const void*  ei      = d_in[1];
    const float* beta    = (const float*)d_in[2];
    const float* W_gat   = (const float*)d_in[3];
    const float* att_src = (const float*)d_in[4];
    const float* att_dst = (const float*)d_in[5];
    const float* bias    = (const float*)d_in[6];
    const float* W_fixed = (const float*)d_in[7];
    float* out = (float*)d_out;

    static int smem_set = 0;
    if (!smem_set) {
        cudaFuncSetAttribute(k_gemm_tc,
                             cudaFuncAttributeMaxDynamicSharedMemorySize,
                             SMEM_GEMM);
        smem_set = 1;
    }

    k_sniff<<<1, 32>>>((const int*)ei);
    k_zero_misc<<<(N_NODES + 255) / 256, 256>>>();
    k_convert_hist<<<(N_EDGES + 255) / 256, 256>>>(ei);

    {   // dual GEMM + fused attention dots
        dim3 grid((N_NODES + GBM - 1) / GBM, 2);
        k_gemm_tc<<<grid, 256, SMEM_GEMM>>>(x, W_gat, W_fixed, att_src, att_dst);
    }

    // CSR build
    k_scan1<<<NCHUNK, SCAN_B>>>();
    k_scan2<<<1, 128>>>();
    k_scan3<<<NCHUNK, SCAN_B>>>();
    k_scatter<<<(N_EDGES + 255) / 256, 256>>>(beta);

    // fused aggregation + bias + ELU
    k_agg<<<(N_NODES * 32 + 255) / 256, 256>>>(bias, out);
}

// round 4
// speedup vs baseline: 2.9206x; 1.2179x over previous
#include <cuda_runtime.h>
#include <cuda_bf16.h>
#include <math.h>
#include <stdint.h>

// ---------------- problem constants ----------------
#define N_NODES   100000
#define N_EDGES   1600000
#define IN_DIM    256
#define OUT_DIM   128
#define NEG_SLOPE 0.2f
#define LAMBDA    0.5f
#define EPS_      1e-8f

// ---------------- device scratch (static, no allocs) ----------------
__device__ float g_h [(size_t)N_NODES * OUT_DIM];   // x @ W_gat^T
__device__ float g_xw[(size_t)N_NODES * OUT_DIM];   // x @ W_fixed^T
__device__ float g_asrc[N_NODES];
__device__ float g_adst[N_NODES];
__device__ int   g_src[N_EDGES];
__device__ int   g_dst[N_EDGES];
__device__ int   g_deg[N_NODES];
__device__ int   g_off[N_NODES];
__device__ int   g_cursor[N_NODES];
__device__ int   g_csr_src[N_EDGES];
__device__ float g_csr_beta[N_EDGES];
__device__ int   g_is64;

#define SCAN_B 1024
#define NCHUNK ((N_NODES + SCAN_B - 1) / SCAN_B)   // 98
__device__ int g_bsum[NCHUNK];

// ---------------- kernel 0: sniff edge_index dtype ----------------
__global__ void k_sniff(const int* __restrict__ ei_words) {
    if (threadIdx.x == 0 && blockIdx.x == 0) {
        int allzero = 1;
        #pragma unroll 1
        for (int i = 0; i < 64; i++) {
            if (ei_words[2 * i + 1] != 0) { allzero = 0; break; }
        }
        g_is64 = allzero;
    }
}

// ---------------- kernel 1: zero small scratch ----------------
__global__ void k_zero_misc() {
    int i = blockIdx.x * blockDim.x + threadIdx.x;
    if (i < N_NODES) {
        g_deg[i] = 0;
        g_cursor[i] = 0;
        g_asrc[i] = 0.0f;
        g_adst[i] = 0.0f;
    }
}

// ---------------- kernel 2: convert edges + degree histogram ----------------
__global__ void k_convert_hist(const void* __restrict__ ei) {
    int e = blockIdx.x * blockDim.x + threadIdx.x;
    if (e >= N_EDGES) return;
    int s, d;
    if (g_is64) {
        const long long* p = (const long long*)ei;
        s = (int)p[e];
        d = (int)p[(size_t)N_EDGES + e];
    } else {
        const int* p = (const int*)ei;
        s = p[e];
        d = p[N_EDGES + e];
    }
    g_src[e] = s;
    g_dst[e] = d;
    atomicAdd(&g_deg[d], 1);
}

// ---------------- bf16 split helpers ----------------
__device__ __forceinline__ void bf16_split(float v, __nv_bfloat16& hi,
                                           __nv_bfloat16& lo) {
    hi = __float2bfloat16(v);
    lo = __float2bfloat16(v - __bfloat162float(hi));
}

__device__ __forceinline__ void mma_bf16(float* d, const uint32_t* a,
                                         uint32_t b0, uint32_t b1) {
    asm volatile(
        "mma.sync.aligned.m16n8k16.row.col.f32.bf16.bf16.f32 "
        "{%0,%1,%2,%3}, {%4,%5,%6,%7}, {%8,%9}, {%0,%1,%2,%3};\n"
        : "+f"(d[0]), "+f"(d[1]), "+f"(d[2]), "+f"(d[3])
        : "r"(a[0]), "r"(a[1]), "r"(a[2]), "r"(a[3]), "r"(b0), "r"(b1));
}

// ---------------- kernel 3: dual GEMM on tensor cores (bf16x3) ----------------
// C[m][n] = sum_k X[m][k]*W[n][k] via 3-term bf16 split (hh + lh + hl).
// CTA tile 128x128, BK=64, 8 warps (4M x 2N), warp tile 32x64.
// Row stride 72 bf16 (144B) -> fragment LDS bank = 4*gid + tig + c = lane: conflict-free.
#define GBM 128
#define GBK 64
#define PADK 72
#define SMEM_GEMM (4 * GBM * PADK * (int)sizeof(__nv_bfloat16))   // 73728 bytes

__global__ __launch_bounds__(256, 2)
void k_gemm_tc(const float* __restrict__ X,
               const float* __restrict__ Wg,
               const float* __restrict__ Wf,
               const float* __restrict__ att_s,
               const float* __restrict__ att_d) {
    extern __shared__ __nv_bfloat16 smem[];
    __nv_bfloat16 (*Ahi)[PADK] = (__nv_bfloat16(*)[PADK])(smem);
    __nv_bfloat16 (*Alo)[PADK] = (__nv_bfloat16(*)[PADK])(smem + 1 * GBM * PADK);
    __nv_bfloat16 (*Bhi)[PADK] = (__nv_bfloat16(*)[PADK])(smem + 2 * GBM * PADK);
    __nv_bfloat16 (*Blo)[PADK] = (__nv_bfloat16(*)[PADK])(smem + 3 * GBM * PADK);

    const float* W = (blockIdx.y == 0) ? Wg : Wf;
    float*       C = (blockIdx.y == 0) ? g_h : g_xw;

    const int row0 = blockIdx.x * GBM;
    const int tid  = threadIdx.x;
    const int warp = tid >> 5, lane = tid & 31;
    const int wm = warp & 3;
    const int wn = warp >> 2;
    const int gid = lane >> 2;    // 0..7
    const int tig = lane & 3;     // 0..3

    float acc[2][8][4];
    #pragma unroll
    for (int mi = 0; mi < 2; mi++)
        #pragma unroll
        for (int ni = 0; ni < 8; ni++)
            #pragma unroll
            for (int j = 0; j < 4; j++) acc[mi][ni][j] = 0.0f;

    for (int k0 = 0; k0 < IN_DIM; k0 += GBK) {
        // ---- fill A tile (128 rows x 64 k): 2048 float4 / 256 thr = 8 each
        #pragma unroll
        for (int i = 0; i < 8; i++) {
            int idx = tid + i * 256;          // 0..2047
            int m   = idx >> 4;               // 0..127
            int k4  = (idx & 15) << 2;        // 0,4,..,60
            float4 v = make_float4(0.f, 0.f, 0.f, 0.f);
            if (row0 + m < N_NODES)
                v = *(const float4*)(X + (size_t)(row0 + m) * IN_DIM + k0 + k4);
            __nv_bfloat16 h, l;
            bf16_split(v.x, h, l); Ahi[m][k4+0] = h; Alo[m][k4+0] = l;
            bf16_split(v.y, h, l); Ahi[m][k4+1] = h; Alo[m][k4+1] = l;
            bf16_split(v.z, h, l); Ahi[m][k4+2] = h; Alo[m][k4+2] = l;
            bf16_split(v.w, h, l); Ahi[m][k4+3] = h; Alo[m][k4+3] = l;
        }
        // ---- fill B tile (128 n-rows x 64 k)
        #pragma unroll
        for (int i = 0; i < 8; i++) {
            int idx = tid + i * 256;
            int n   = idx >> 4;
            int k4  = (idx & 15) << 2;
            float4 v = *(const float4*)(W + (size_t)n * IN_DIM + k0 + k4);
            __nv_bfloat16 h, l;
            bf16_split(v.x, h, l); Bhi[n][k4+0] = h; Blo[n][k4+0] = l;
            bf16_split(v.y, h, l); Bhi[n][k4+1] = h; Blo[n][k4+1] = l;
            bf16_split(v.z, h, l); Bhi[n][k4+2] = h; Blo[n][k4+2] = l;
            bf16_split(v.w, h, l); Bhi[n][k4+3] = h; Blo[n][k4+3] = l;
        }
        __syncthreads();

        #pragma unroll
        for (int ks = 0; ks < 4; ks++) {
            const int kk = ks * 16;
            // A fragments (hi, lo) for both 16-row sub-tiles
            uint32_t ah[2][4], al[2][4];
            #pragma unroll
            for (int mi = 0; mi < 2; mi++) {
                int r = wm * 32 + mi * 16 + gid;
                ah[mi][0] = *(const uint32_t*)&Ahi[r    ][kk + 2*tig    ];
                ah[mi][1] = *(const uint32_t*)&Ahi[r + 8][kk + 2*tig    ];
                ah[mi][2] = *(const uint32_t*)&Ahi[r    ][kk + 2*tig + 8];
                ah[mi][3] = *(const uint32_t*)&Ahi[r + 8][kk + 2*tig + 8];
                al[mi][0] = *(const uint32_t*)&Alo[r    ][kk + 2*tig    ];
                al[mi][1] = *(const uint32_t*)&Alo[r + 8][kk + 2*tig    ];
                al[mi][2] = *(const uint32_t*)&Alo[r    ][kk + 2*tig + 8];
                al[mi][3] = *(const uint32_t*)&Alo[r + 8][kk + 2*tig + 8];
            }
            #pragma unroll
            for (int ni = 0; ni < 8; ni++) {
                int n = wn * 64 + ni * 8 + gid;
                uint32_t bh0 = *(const uint32_t*)&Bhi[n][kk + 2*tig    ];
                uint32_t bh1 = *(const uint32_t*)&Bhi[n][kk + 2*tig + 8];
                uint32_t bl0 = *(const uint32_t*)&Blo[n][kk + 2*tig    ];
                uint32_t bl1 = *(const uint32_t*)&Blo[n][kk + 2*tig + 8];
                #pragma unroll
                for (int mi = 0; mi < 2; mi++) {
                    mma_bf16(acc[mi][ni], ah[mi], bh0, bh1);   // hi*hi
                    mma_bf16(acc[mi][ni], al[mi], bh0, bh1);   // lo*hi
                    mma_bf16(acc[mi][ni], ah[mi], bl0, bl1);   // hi*lo
                }
            }
        }
        __syncthreads();
    }

    // ---- epilogue: store C ----
    #pragma unroll
    for (int mi = 0; mi < 2; mi++) {
        #pragma unroll
        for (int ni = 0; ni < 8; ni++) {
            int col = wn * 64 + ni * 8 + 2 * tig;
            int r0  = row0 + wm * 32 + mi * 16 + gid;
            if (r0 < N_NODES)
                *(float2*)(C + (size_t)r0 * OUT_DIM + col) =
                    make_float2(acc[mi][ni][0], acc[mi][ni][1]);
            int r1 = r0 + 8;
            if (r1 < N_NODES)
                *(float2*)(C + (size_t)r1 * OUT_DIM + col) =
                    make_float2(acc[mi][ni][2], acc[mi][ni][3]);
        }
    }

    // ---- fused attention dots (h branch only) ----
    if (blockIdx.y == 0) {
        #pragma unroll
        for (int mi = 0; mi < 2; mi++) {
            float s0 = 0.f, d0 = 0.f, s1 = 0.f, d1 = 0.f;
            #pragma unroll
            for (int ni = 0; ni < 8; ni++) {
                int col = wn * 64 + ni * 8 + 2 * tig;
                float a0 = __ldg(att_s + col), a1 = __ldg(att_s + col + 1);
                float b0 = __ldg(att_d + col), b1 = __ldg(att_d + col + 1);
                s0 += acc[mi][ni][0] * a0 + acc[mi][ni][1] * a1;
                d0 += acc[mi][ni][0] * b0 + acc[mi][ni][1] * b1;
                s1 += acc[mi][ni][2] * a0 + acc[mi][ni][3] * a1;
                d1 += acc[mi][ni][2] * b0 + acc[mi][ni][3] * b1;
            }
            #pragma unroll
            for (int o = 1; o <= 2; o <<= 1) {
                s0 += __shfl_xor_sync(0xffffffffu, s0, o);
                d0 += __shfl_xor_sync(0xffffffffu, d0, o);
                s1 += __shfl_xor_sync(0xffffffffu, s1, o);
                d1 += __shfl_xor_sync(0xffffffffu, d1, o);
            }
            if (tig == 0) {
                int r0 = row0 + wm * 32 + mi * 16 + gid;
                if (r0 < N_NODES) {
                    atomicAdd(&g_asrc[r0], s0);
                    atomicAdd(&g_adst[r0], d0);
                }
                int r1 = r0 + 8;
                if (r1 < N_NODES) {
                    atomicAdd(&g_asrc[r1], s1);
                    atomicAdd(&g_adst[r1], d1);
                }
            }
        }
    }
}

// ---------------- scan kernels (exclusive prefix of g_deg -> g_off) --------
__global__ void k_scan1() {
    __shared__ int sh[SCAN_B];
    int i = blockIdx.x * SCAN_B + threadIdx.x;
    int v = (i < N_NODES) ? g_deg[i] : 0;
    sh[threadIdx.x] = v;
    __syncthreads();
    for (int o = 1; o < SCAN_B; o <<= 1) {
        int t = (threadIdx.x >= o) ? sh[threadIdx.x - o] : 0;
        __syncthreads();
        sh[threadIdx.x] += t;
        __syncthreads();
    }
    if (i < N_NODES) g_off[i] = sh[threadIdx.x] - v;
    if (threadIdx.x == SCAN_B - 1) g_bsum[blockIdx.x] = sh[threadIdx.x];
}

__global__ void k_scan2() {
    __shared__ int sh[128];
    int v = (threadIdx.x < NCHUNK) ? g_bsum[threadIdx.x] : 0;
    sh[threadIdx.x] = v;
    __syncthreads();
    for (int o = 1; o < 128; o <<= 1) {
        int t = (threadIdx.x >= o) ? sh[threadIdx.x - o] : 0;
        __syncthreads();
        sh[threadIdx.x] += t;
        __syncthreads();
    }
    if (threadIdx.x < NCHUNK) g_bsum[threadIdx.x] = sh[threadIdx.x] - v;
}

__global__ void k_scan3() {
    int i = blockIdx.x * SCAN_B + threadIdx.x;
    if (i < N_NODES) g_off[i] += g_bsum[blockIdx.x];
}

// ---------------- kernel: scatter edges into CSR ----------------
__global__ void k_scatter(const float* __restrict__ beta) {
    int e = blockIdx.x * blockDim.x + threadIdx.x;
    if (e >= N_EDGES) return;
    int d = g_dst[e];
    int pos = g_off[d] + atomicAdd(&g_cursor[d], 1);
    g_csr_src[pos]  = g_src[e];
    g_csr_beta[pos] = beta[e];
}

// ---------------- kernel: warp-per-node fused aggregation ----------------
__global__ __launch_bounds__(256)
void k_agg(const float* __restrict__ bias, float* __restrict__ out) {
    int node = (blockIdx.x * blockDim.x + threadIdx.x) >> 5;
    if (node >= N_NODES) return;
    int lane = threadIdx.x & 31;

    int beg = g_off[node];
    int deg = g_deg[node];
    float adst = g_adst[node];

    // phase 1: denom via lane-parallel alpha + warp reduce
    float psum = 0.0f;
    for (int i = beg + lane; i < beg + deg; i += 32) {
        int s = g_csr_src[i];
        float xv = g_asrc[s] + adst;
        if (xv < 0.0f) xv *= NEG_SLOPE;
        psum += 1.0f / (1.0f + expf(-xv));
    }
    #pragma unroll
    for (int o = 16; o; o >>= 1) psum += __shfl_xor_sync(0xffffffffu, psum, o);
    float invden = LAMBDA / (psum + EPS_);

    // phase 2: accumulate lam*alpha*h[src] + (1-lam)*beta*xw[src]
    float4 acc = make_float4(0.f, 0.f, 0.f, 0.f);
    #pragma unroll 2
    for (int i = beg; i < beg + deg; i++) {
        int s   = g_csr_src[i];           // warp-uniform broadcast load
        float b = g_csr_beta[i];
        float xv = g_asrc[s] + adst;
        if (xv < 0.0f) xv *= NEG_SLOPE;
        float al = 1.0f / (1.0f + expf(-xv));
        float cA = al * invden;
        float cB = (1.0f - LAMBDA) * b;
        float4 h4 = __ldg((const float4*)(g_h  + (size_t)s * OUT_DIM) + lane);
        float4 x4 = __ldg((const float4*)(g_xw + (size_t)s * OUT_DIM) + lane);
        acc.x += cA * h4.x + cB * x4.x;
        acc.y += cA * h4.y + cB * x4.y;
        acc.z += cA * h4.z + cB * x4.z;
        acc.w += cA * h4.w + cB * x4.w;
    }

    // epilogue: + lam*bias, ELU, single store
    float4 bv = *(const float4*)(bias + lane * 4);
    float4 v;
    v.x = acc.x + LAMBDA * bv.x;
    v.y = acc.y + LAMBDA * bv.y;
    v.z = acc.z + LAMBDA * bv.z;
    v.w = acc.w + LAMBDA * bv.w;
    v.x = (v.x > 0.0f) ? v.x : expm1f(v.x);
    v.y = (v.y > 0.0f) ? v.y : expm1f(v.y);
    v.z = (v.z > 0.0f) ? v.z : expm1f(v.z);
    v.w = (v.w > 0.0f) ? v.w : expm1f(v.w);
    *(float4*)(out + (size_t)node * OUT_DIM + lane * 4) = v;
}

// ---------------- launch ----------------
extern "C" void kernel_launch(void* const* d_in, const int* in_sizes, int n_in,
                              void* d_out, int out_size) {
    const float* x       = (const float*)d_in[0];
    const void*  ei      = d_in[1];
    const float* beta    = (const float*)d_in[2];
    const float* W_gat   = (const float*)d_in[3];
    const float* att_src = (const float*)d_in[4];
    const float* att_dst = (const float*)d_in[5];
    const float* bias    = (const float*)d_in[6];
    const float* W_fixed = (const float*)d_in[7];
    float* out = (float*)d_out;

    static int smem_set = 0;
    if (!smem_set) {
        cudaFuncSetAttribute(k_gemm_tc,
                             cudaFuncAttributeMaxDynamicSharedMemorySize,
                             SMEM_GEMM);
        smem_set = 1;
    }

    k_sniff<<<1, 32>>>((const int*)ei);
    k_zero_misc<<<(N_NODES + 255) / 256, 256>>>();
    k_convert_hist<<<(N_EDGES + 255) / 256, 256>>>(ei);

    {   // dual GEMM + fused attention dots
        dim3 grid((N_NODES + GBM - 1) / GBM, 2);
        k_gemm_tc<<<grid, 256, SMEM_GEMM>>>(x, W_gat, W_fixed, att_src, att_dst);
    }

    // CSR build
    k_scan1<<<NCHUNK, SCAN_B>>>();
    k_scan2<<<1, 128>>>();
    k_scan3<<<NCHUNK, SCAN_B>>>();
    k_scatter<<<(N_EDGES + 255) / 256, 256>>>(beta);

    // fused aggregation + bias + ELU
    k_agg<<<(N_NODES * 32 + 255) / 256, 256>>>(bias, out);
}

// round 5
// speedup vs baseline: 3.1038x; 1.0627x over previous
#include <cuda_runtime.h>
#include <cuda_bf16.h>
#include <math.h>
#include <stdint.h>

// ---------------- problem constants ----------------
#define N_NODES   100000
#define N_EDGES   1600000
#define IN_DIM    256
#define OUT_DIM   128
#define NEG_SLOPE 0.2f
#define LAMBDA    0.5f
#define EPS_      1e-8f

// ---------------- device scratch (static, no allocs) ----------------
__device__ float g_h [(size_t)N_NODES * OUT_DIM];   // x @ W_gat^T
__device__ float g_xw[(size_t)N_NODES * OUT_DIM];   // x @ W_fixed^T
__device__ float g_asrc[N_NODES];
__device__ float g_adst[N_NODES];
__device__ int   g_deg[N_NODES];
__device__ int   g_off[N_NODES];
__device__ int   g_cursor[N_NODES];
__device__ int   g_csr_src[N_EDGES];
__device__ float g_csr_beta[N_EDGES];
__device__ int   g_is64;

#define SCAN_B 1024
#define NCHUNK ((N_NODES + SCAN_B - 1) / SCAN_B)   // 98
__device__ int g_bsum[NCHUNK];

// ---------------- kernel 0: sniff edge_index dtype ----------------
__global__ void k_sniff(const int* __restrict__ ei_words) {
    if (threadIdx.x == 0 && blockIdx.x == 0) {
        int allzero = 1;
        #pragma unroll 1
        for (int i = 0; i < 64; i++) {
            if (ei_words[2 * i + 1] != 0) { allzero = 0; break; }
        }
        g_is64 = allzero;
    }
}

// ---------------- kernel 1: zero small scratch ----------------
__global__ void k_zero_misc() {
    int i = blockIdx.x * blockDim.x + threadIdx.x;
    if (i < N_NODES) {
        g_deg[i] = 0;
        g_cursor[i] = 0;
        g_asrc[i] = 0.0f;
        g_adst[i] = 0.0f;
    }
}

// ---------------- edge decode helpers ----------------
__device__ __forceinline__ int edge_at(const void* ei, size_t idx) {
    return g_is64 ? (int)((const long long*)ei)[idx]
                  : ((const int*)ei)[idx];
}

// ---------------- kernel: degree histogram (direct from ei) ----------------
__global__ void k_hist(const void* __restrict__ ei) {
    int e = blockIdx.x * blockDim.x + threadIdx.x;
    if (e >= N_EDGES) return;
    int d = edge_at(ei, (size_t)N_EDGES + e);
    atomicAdd(&g_deg[d], 1);
}

// ---------------- bf16 split-pack: float4 -> hi uint2 + lo uint2 ----------
__device__ __forceinline__ uint2 split_pack4(float4 v, uint2& lo_out) {
    float2 p0 = make_float2(v.x, v.y);
    float2 p1 = make_float2(v.z, v.w);
    __nv_bfloat162 h0 = __float22bfloat162_rn(p0);
    __nv_bfloat162 h1 = __float22bfloat162_rn(p1);
    float2 b0 = __bfloat1622float2(h0);
    float2 b1 = __bfloat1622float2(h1);
    __nv_bfloat162 l0 = __float22bfloat162_rn(make_float2(p0.x - b0.x, p0.y - b0.y));
    __nv_bfloat162 l1 = __float22bfloat162_rn(make_float2(p1.x - b1.x, p1.y - b1.y));
    lo_out = make_uint2(*(uint32_t*)&l0, *(uint32_t*)&l1);
    return make_uint2(*(uint32_t*)&h0, *(uint32_t*)&h1);
}

__device__ __forceinline__ void mma_bf16(float* d, const uint32_t* a,
                                         uint32_t b0, uint32_t b1) {
    asm volatile(
        "mma.sync.aligned.m16n8k16.row.col.f32.bf16.bf16.f32 "
        "{%0,%1,%2,%3}, {%4,%5,%6,%7}, {%8,%9}, {%0,%1,%2,%3};\n"
        : "+f"(d[0]), "+f"(d[1]), "+f"(d[2]), "+f"(d[3])
        : "r"(a[0]), "r"(a[1]), "r"(a[2]), "r"(a[3]), "r"(b0), "r"(b1));
}

// ---------------- kernel: dual GEMM on tensor cores (bf16x3) ----------------
// C[m][n] = sum_k X[m][k]*W[n][k] via 3-term bf16 split (hh + lh + hl).
// CTA tile 128x128, BK=64, 8 warps (4M x 2N), warp tile 32x64.
// Row stride 72 bf16 (144B): fragment LDS bank = lane id -> conflict-free;
// 144 % 8 == 0 so packed uint2 (STS.64) tile-fill stores stay 8B-aligned.
#define GBM 128
#define GBK 64
#define PADK 72
#define SMEM_GEMM (4 * GBM * PADK * (int)sizeof(__nv_bfloat16))   // 73728 bytes

__global__ __launch_bounds__(256, 2)
void k_gemm_tc(const float* __restrict__ X,
               const float* __restrict__ Wg,
               const float* __restrict__ Wf,
               const float* __restrict__ att_s,
               const float* __restrict__ att_d) {
    extern __shared__ __nv_bfloat16 smem[];
    __nv_bfloat16 (*Ahi)[PADK] = (__nv_bfloat16(*)[PADK])(smem);
    __nv_bfloat16 (*Alo)[PADK] = (__nv_bfloat16(*)[PADK])(smem + 1 * GBM * PADK);
    __nv_bfloat16 (*Bhi)[PADK] = (__nv_bfloat16(*)[PADK])(smem + 2 * GBM * PADK);
    __nv_bfloat16 (*Blo)[PADK] = (__nv_bfloat16(*)[PADK])(smem + 3 * GBM * PADK);

    const float* W = (blockIdx.y == 0) ? Wg : Wf;
    float*       C = (blockIdx.y == 0) ? g_h : g_xw;

    const int row0 = blockIdx.x * GBM;
    const int tid  = threadIdx.x;
    const int warp = tid >> 5, lane = tid & 31;
    const int wm = warp & 3;
    const int wn = warp >> 2;
    const int gid = lane >> 2;    // 0..7
    const int tig = lane & 3;     // 0..3

    float acc[2][8][4];
    #pragma unroll
    for (int mi = 0; mi < 2; mi++)
        #pragma unroll
        for (int ni = 0; ni < 8; ni++)
            #pragma unroll
            for (int j = 0; j < 4; j++) acc[mi][ni][j] = 0.0f;

    for (int k0 = 0; k0 < IN_DIM; k0 += GBK) {
        // ---- fill A tile (128 rows x 64 k): 2048 float4 / 256 thr = 8 each
        #pragma unroll
        for (int i = 0; i < 8; i++) {
            int idx = tid + i * 256;          // 0..2047
            int m   = idx >> 4;               // 0..127
            int k4  = (idx & 15) << 2;        // 0,4,..,60
            float4 v = make_float4(0.f, 0.f, 0.f, 0.f);
            if (row0 + m < N_NODES)
                v = *(const float4*)(X + (size_t)(row0 + m) * IN_DIM + k0 + k4);
            uint2 lo;
            uint2 hi = split_pack4(v, lo);
            *(uint2*)&Ahi[m][k4] = hi;
            *(uint2*)&Alo[m][k4] = lo;
        }
        // ---- fill B tile (128 n-rows x 64 k)
        #pragma unroll
        for (int i = 0; i < 8; i++) {
            int idx = tid + i * 256;
            int n   = idx >> 4;
            int k4  = (idx & 15) << 2;
            float4 v = *(const float4*)(W + (size_t)n * IN_DIM + k0 + k4);
            uint2 lo;
            uint2 hi = split_pack4(v, lo);
            *(uint2*)&Bhi[n][k4] = hi;
            *(uint2*)&Blo[n][k4] = lo;
        }
        __syncthreads();

        #pragma unroll
        for (int ks = 0; ks < 4; ks++) {
            const int kk = ks * 16;
            uint32_t ah[2][4], al[2][4];
            #pragma unroll
            for (int mi = 0; mi < 2; mi++) {
                int r = wm * 32 + mi * 16 + gid;
                ah[mi][0] = *(const uint32_t*)&Ahi[r    ][kk + 2*tig    ];
                ah[mi][1] = *(const uint32_t*)&Ahi[r + 8][kk + 2*tig    ];
                ah[mi][2] = *(const uint32_t*)&Ahi[r    ][kk + 2*tig + 8];
                ah[mi][3] = *(const uint32_t*)&Ahi[r + 8][kk + 2*tig + 8];
                al[mi][0] = *(const uint32_t*)&Alo[r    ][kk + 2*tig    ];
                al[mi][1] = *(const uint32_t*)&Alo[r + 8][kk + 2*tig    ];
                al[mi][2] = *(const uint32_t*)&Alo[r    ][kk + 2*tig + 8];
                al[mi][3] = *(const uint32_t*)&Alo[r + 8][kk + 2*tig + 8];
            }
            #pragma unroll
            for (int ni = 0; ni < 8; ni++) {
                int n = wn * 64 + ni * 8 + gid;
                uint32_t bh0 = *(const uint32_t*)&Bhi[n][kk + 2*tig    ];
                uint32_t bh1 = *(const uint32_t*)&Bhi[n][kk + 2*tig + 8];
                uint32_t bl0 = *(const uint32_t*)&Blo[n][kk + 2*tig    ];
                uint32_t bl1 = *(const uint32_t*)&Blo[n][kk + 2*tig + 8];
                #pragma unroll
                for (int mi = 0; mi < 2; mi++) {
                    mma_bf16(acc[mi][ni], ah[mi], bh0, bh1);   // hi*hi
                    mma_bf16(acc[mi][ni], al[mi], bh0, bh1);   // lo*hi
                    mma_bf16(acc[mi][ni], ah[mi], bl0, bl1);   // hi*lo
                }
            }
        }
        __syncthreads();
    }

    // ---- epilogue: store C ----
    #pragma unroll
    for (int mi = 0; mi < 2; mi++) {
        #pragma unroll
        for (int ni = 0; ni < 8; ni++) {
            int col = wn * 64 + ni * 8 + 2 * tig;
            int r0  = row0 + wm * 32 + mi * 16 + gid;
            if (r0 < N_NODES)
                *(float2*)(C + (size_t)r0 * OUT_DIM + col) =
                    make_float2(acc[mi][ni][0], acc[mi][ni][1]);
            int r1 = r0 + 8;
            if (r1 < N_NODES)
                *(float2*)(C + (size_t)r1 * OUT_DIM + col) =
                    make_float2(acc[mi][ni][2], acc[mi][ni][3]);
        }
    }

    // ---- fused attention dots (h branch only) ----
    if (blockIdx.y == 0) {
        #pragma unroll
        for (int mi = 0; mi < 2; mi++) {
            float s0 = 0.f, d0 = 0.f, s1 = 0.f, d1 = 0.f;
            #pragma unroll
            for (int ni = 0; ni < 8; ni++) {
                int col = wn * 64 + ni * 8 + 2 * tig;
                float a0 = __ldg(att_s + col), a1 = __ldg(att_s + col + 1);
                float b0 = __ldg(att_d + col), b1 = __ldg(att_d + col + 1);
                s0 += acc[mi][ni][0] * a0 + acc[mi][ni][1] * a1;
                d0 += acc[mi][ni][0] * b0 + acc[mi][ni][1] * b1;
                s1 += acc[mi][ni][2] * a0 + acc[mi][ni][3] * a1;
                d1 += acc[mi][ni][2] * b0 + acc[mi][ni][3] * b1;
            }
            #pragma unroll
            for (int o = 1; o <= 2; o <<= 1) {
                s0 += __shfl_xor_sync(0xffffffffu, s0, o);
                d0 += __shfl_xor_sync(0xffffffffu, d0, o);
                s1 += __shfl_xor_sync(0xffffffffu, s1, o);
                d1 += __shfl_xor_sync(0xffffffffu, d1, o);
            }
            if (tig == 0) {
                int r0 = row0 + wm * 32 + mi * 16 + gid;
                if (r0 < N_NODES) {
                    atomicAdd(&g_asrc[r0], s0);
                    atomicAdd(&g_adst[r0], d0);
                }
                int r1 = r0 + 8;
                if (r1 < N_NODES) {
                    atomicAdd(&g_asrc[r1], s1);
                    atomicAdd(&g_adst[r1], d1);
                }
            }
        }
    }
}

// ---------------- scan kernels (exclusive prefix of g_deg -> g_off) --------
__global__ void k_scan1() {
    __shared__ int sh[SCAN_B];
    int i = blockIdx.x * SCAN_B + threadIdx.x;
    int v = (i < N_NODES) ? g_deg[i] : 0;
    sh[threadIdx.x] = v;
    __syncthreads();
    for (int o = 1; o < SCAN_B; o <<= 1) {
        int t = (threadIdx.x >= o) ? sh[threadIdx.x - o] : 0;
        __syncthreads();
        sh[threadIdx.x] += t;
        __syncthreads();
    }
    if (i < N_NODES) g_off[i] = sh[threadIdx.x] - v;
    if (threadIdx.x == SCAN_B - 1) g_bsum[blockIdx.x] = sh[threadIdx.x];
}

__global__ void k_scan2() {
    __shared__ int sh[128];
    int v = (threadIdx.x < NCHUNK) ? g_bsum[threadIdx.x] : 0;
    sh[threadIdx.x] = v;
    __syncthreads();
    for (int o = 1; o < 128; o <<= 1) {
        int t = (threadIdx.x >= o) ? sh[threadIdx.x - o] : 0;
        __syncthreads();
        sh[threadIdx.x] += t;
        __syncthreads();
    }
    if (threadIdx.x < NCHUNK) g_bsum[threadIdx.x] = sh[threadIdx.x] - v;
}

__global__ void k_scan3() {
    int i = blockIdx.x * SCAN_B + threadIdx.x;
    if (i < N_NODES) g_off[i] += g_bsum[blockIdx.x];
}

// ---------------- kernel: scatter edges into CSR (direct from ei) ---------
__global__ void k_scatter(const void* __restrict__ ei,
                          const float* __restrict__ beta) {
    int e = blockIdx.x * blockDim.x + threadIdx.x;
    if (e >= N_EDGES) return;
    int s = edge_at(ei, e);
    int d = edge_at(ei, (size_t)N_EDGES + e);
    int pos = g_off[d] + atomicAdd(&g_cursor[d], 1);
    g_csr_src[pos]  = s;
    g_csr_beta[pos] = beta[e];
}

// ---------------- kernel: warp-per-node fused aggregation ----------------
__global__ __launch_bounds__(256)
void k_agg(const float* __restrict__ bias, float* __restrict__ out) {
    int node = (blockIdx.x * blockDim.x + threadIdx.x) >> 5;
    if (node >= N_NODES) return;
    int lane = threadIdx.x & 31;

    int beg = g_off[node];
    int deg = g_deg[node];
    float adst = g_adst[node];

    // phase 1: denom via lane-parallel alpha + warp reduce
    float psum = 0.0f;
    for (int i = beg + lane; i < beg + deg; i += 32) {
        int s = g_csr_src[i];
        float xv = g_asrc[s] + adst;
        if (xv < 0.0f) xv *= NEG_SLOPE;
        psum += 1.0f / (1.0f + expf(-xv));
    }
    #pragma unroll
    for (int o = 16; o; o >>= 1) psum += __shfl_xor_sync(0xffffffffu, psum, o);
    float invden = LAMBDA / (psum + EPS_);

    // phase 2: accumulate lam*alpha*h[src] + (1-lam)*beta*xw[src]
    float4 acc = make_float4(0.f, 0.f, 0.f, 0.f);
    #pragma unroll 2
    for (int i = beg; i < beg + deg; i++) {
        int s   = g_csr_src[i];           // warp-uniform broadcast load
        float b = g_csr_beta[i];
        float xv = g_asrc[s] + adst;
        if (xv < 0.0f) xv *= NEG_SLOPE;
        float al = 1.0f / (1.0f + expf(-xv));
        float cA = al * invden;
        float cB = (1.0f - LAMBDA) * b;
        float4 h4 = __ldg((const float4*)(g_h  + (size_t)s * OUT_DIM) + lane);
        float4 x4 = __ldg((const float4*)(g_xw + (size_t)s * OUT_DIM) + lane);
        acc.x += cA * h4.x + cB * x4.x;
        acc.y += cA * h4.y + cB * x4.y;
        acc.z += cA * h4.z + cB * x4.z;
        acc.w += cA * h4.w + cB * x4.w;
    }

    // epilogue: + lam*bias, ELU, single store
    float4 bv = *(const float4*)(bias + lane * 4);
    float4 v;
    v.x = acc.x + LAMBDA * bv.x;
    v.y = acc.y + LAMBDA * bv.y;
    v.z = acc.z + LAMBDA * bv.z;
    v.w = acc.w + LAMBDA * bv.w;
    v.x = (v.x > 0.0f) ? v.x : expm1f(v.x);
    v.y = (v.y > 0.0f) ? v.y : expm1f(v.y);
    v.z = (v.z > 0.0f) ? v.z : expm1f(v.z);
    v.w = (v.w > 0.0f) ? v.w : expm1f(v.w);
    *(float4*)(out + (size_t)node * OUT_DIM + lane * 4) = v;
}

// ---------------- launch ----------------
extern "C" void kernel_launch(void* const* d_in, const int* in_sizes, int n_in,
                              void* d_out, int out_size) {
    const float* x       = (const float*)d_in[0];
    const void*  ei      = d_in[1];
    const float* beta    = (const float*)d_in[2];
    const float* W_gat   = (const float*)d_in[3];
    const float* att_src = (const float*)d_in[4];
    const float* att_dst = (const float*)d_in[5];
    const float* bias    = (const float*)d_in[6];
    const float* W_fixed = (const float*)d_in[7];
    float* out = (float*)d_out;

    static cudaStream_t s2 = nullptr;
    static cudaEvent_t evFork = nullptr, evJoin = nullptr;
    static int init_done = 0;
    if (!init_done) {
        cudaFuncSetAttribute(k_gemm_tc,
                             cudaFuncAttributeMaxDynamicSharedMemorySize,
                             SMEM_GEMM);
        cudaStreamCreateWithFlags(&s2, cudaStreamNonBlocking);
        cudaEventCreateWithFlags(&evFork, cudaEventDisableTiming);
        cudaEventCreateWithFlags(&evJoin, cudaEventDisableTiming);
        init_done = 1;
    }

    // prologue on main stream: zero scratch used by both branches
    k_zero_misc<<<(N_NODES + 255) / 256, 256>>>();

    // ---- fork: CSR build on s2, GEMM on main ----
    cudaEventRecord(evFork, 0);
    cudaStreamWaitEvent(s2, evFork, 0);

    {   // dual GEMM + fused attention dots (main stream)
        dim3 grid((N_NODES + GBM - 1) / GBM, 2);
        k_gemm_tc<<<grid, 256, SMEM_GEMM>>>(x, W_gat, W_fixed, att_src, att_dst);
    }

    // CSR build (side stream, independent of GEMM)
    k_sniff<<<1, 32, 0, s2>>>((const int*)ei);
    k_hist<<<(N_EDGES + 255) / 256, 256, 0, s2>>>(ei);
    k_scan1<<<NCHUNK, SCAN_B, 0, s2>>>();
    k_scan2<<<1, 128, 0, s2>>>();
    k_scan3<<<NCHUNK, SCAN_B, 0, s2>>>();
    k_scatter<<<(N_EDGES + 255) / 256, 256, 0, s2>>>(ei, beta);

    // ---- join ----
    cudaEventRecord(evJoin, s2);
    cudaStreamWaitEvent(0, evJoin, 0);

    // fused aggregation + bias + ELU
    k_agg<<<(N_NODES * 32 + 255) / 256, 256>>>(bias, out);
}